// round 10
// baseline (speedup 1.0000x reference)
#include <cuda_runtime.h>
#include <math.h>

// Problem constants (shapes fixed by setup_inputs)
#define NB 4
#define NC 3
#define HH 768
#define NHP 11          // patches per axis
#define NPATCH 121
#define PSZ 128
#define STR 64
#define KSZ 31
#define KK  961         // 31*31
#define PADD 158        // PSZ + 2*15
#define EPSF 1e-6f

// Scratch (device globals: allocation-free rule)
__device__ float g_xlin[NB*NC*HH*HH];                 // 28.3 MB linearized image
__device__ float g_pout[NB*NPATCH*NC*PSZ*PSZ];        // 95 MB windowed per-patch conv outputs
__device__ float g_basis[15*KK];                      // 14 normalized polys + mask (z=14)
__device__ float g_coef[NPATCH*14];
__device__ float g_kern[NPATCH*NC*KK];                // flipped+shifted normalized PSFs

__device__ __forceinline__ float blockReduce256(float v, float* red) {
    int tid = threadIdx.x;
    red[tid] = v; __syncthreads();
    for (int s = 128; s > 0; s >>= 1) {
        if (tid < s) red[tid] += red[tid + s];
        __syncthreads();
    }
    float r = red[0];
    __syncthreads();
    return r;
}

// Accurate tanh (immune to fast-math tanh.approx)
__device__ __forceinline__ float tanh_acc(float x) {
    float ax = fabsf(x);
    float e = __expf(-2.0f * ax);
    float t = (1.0f - e) / (1.0f + e);
    return copysignf(t, x);
}

// ---------------- Kernel 0: pupil basis ----------------
// Bit-exact emulation of the numpy reference using round-to-nearest intrinsics
// (__ddiv_rn/__dmul_rn/__dadd_rn) so ptxas CANNOT contract into DFMA. The mask
// test r^2 <= 1 sits exactly on the rounding knife-edge for 12 lattice points
// (cardinals + (±0.6,±0.8) family); numpy rounds each op separately:
//   c_i = fl(fl(i * fl(2/30)) + (-1)),  c[30] = 1.0 (linspace endpoint)
//   r2  = fl(fl(x*x) + fl(y*y))
__global__ void k_basis() {
    __shared__ float red[256];
    __shared__ float rmsv[14];
    int tid = threadIdx.x;
    const double step = __ddiv_rn(2.0, 30.0);
    for (int idx = tid; idx < KK; idx += 256) {
        int ii = idx / KSZ, jj = idx % KSZ;
        double x = (jj == 30) ? 1.0 : __dadd_rn(__dmul_rn((double)jj, step), -1.0);
        double y = (ii == 30) ? 1.0 : __dadd_rn(__dmul_rn((double)ii, step), -1.0);
        double r2 = __dadd_rn(__dmul_rn(x, x), __dmul_rn(y, y));
        float m = (r2 <= 1.0) ? 1.0f : 0.0f;
        double pxp[5], pyp[5];
        pxp[0] = 1.0; pyp[0] = 1.0;
        for (int d = 1; d < 5; d++) {
            pxp[d] = __dmul_rn(pxp[d-1], x);
            pyp[d] = __dmul_rn(pyp[d-1], y);
        }
        int z = 0;
        for (int deg = 1; deg <= 4; deg++)
            for (int i2 = 0; i2 <= deg; i2++) {
                // np: stack(polys).astype(f32) * mask
                g_basis[z*KK + idx] = m * (float)__dmul_rn(pxp[deg-i2], pyp[i2]);
                z++;
            }
        g_basis[14*KK + idx] = m;
    }
    __syncthreads();
    float pc = 0.f;
    for (int idx = tid; idx < KK; idx += 256) pc += g_basis[14*KK + idx];
    float msum = blockReduce256(pc, red);   // exact small integer
    for (int z = 0; z < 14; z++) {
        float s = 0.f;
        for (int idx = tid; idx < KK; idx += 256) { float v = g_basis[z*KK + idx]; s += v*v; }
        float tot = blockReduce256(s, red);
        if (tid == 0) rmsv[z] = sqrtf(tot / msum) + 1e-8f;  // f32, matches np (basis is f32 here)
    }
    __syncthreads();
    for (int z = 0; z < 14; z++) {
        float inv = 1.0f / rmsv[z];
        for (int idx = tid; idx < KK; idx += 256) g_basis[z*KK + idx] *= inv;
    }
}

// ---------------- Kernel 1: MLP -> Zernike coeffs (121 unique) ----------------
__global__ void k_mlp(const float* __restrict__ w1, const float* __restrict__ b1,
                      const float* __restrict__ w2, const float* __restrict__ b2,
                      const float* __restrict__ w3, const float* __restrict__ b3) {
    int n = blockIdx.x*blockDim.x + threadIdx.x;
    if (n >= NPATCH) return;
    int i = n / NHP, j = n % NHP;
    float gy = ((float)(i*STR) + 64.0f) / 768.0f * 2.0f - 1.0f;
    float gx = ((float)(j*STR) + 64.0f) / 768.0f * 2.0f - 1.0f;
    float h1[64], h2[64];
    for (int k = 0; k < 64; k++)
        h1[k] = tanh_acc(gy*w1[k] + gx*w1[64 + k] + b1[k]);
    for (int k = 0; k < 64; k++) {
        float s = b2[k];
        for (int m = 0; m < 64; m++) s += h1[m]*w2[m*64 + k];
        h2[k] = tanh_acc(s);
    }
    for (int z = 0; z < 14; z++) {
        float s = b3[z];
        for (int m = 0; m < 64; m++) s += h2[m]*w3[m*14 + z];
        g_coef[n*14 + z] = s;
    }
}

// ---------------- Kernel 2: PSF via separable 31-pt DFT ----------------
// |FFT2(ifftshift(f))| == |DFT2(f)| (shift theorem), and fftshift + [::-1,::-1]
// fold into K[a,b] = p[(15-a)%31, (15-b)%31].
__global__ void k_psf() {
    int n = blockIdx.x, c = blockIdx.y;
    __shared__ float fr[KK], fi[KK], gr2[KK], gi2[KK];
    __shared__ float twr[KSZ], twi[KSZ], cf[14], red[256];
    int tid = threadIdx.x;
    if (tid < KSZ) {
        float sn, cs;
        sincospif(-2.0f * (float)tid / 31.0f, &sn, &cs);
        twr[tid] = cs; twi[tid] = sn;
    }
    if (tid < 14) cf[tid] = g_coef[n*14 + tid];
    __syncthreads();
    float wl = (c == 0) ? (0.53f/0.61f) : ((c == 1) ? 1.0f : (0.53f/0.47f));
    for (int idx = tid; idx < KK; idx += 256) {
        float ph = 0.f;
        #pragma unroll
        for (int z = 0; z < 14; z++) ph += cf[z]*g_basis[z*KK + idx];
        float m = g_basis[14*KK + idx];
        float sn, cs; sincospif(2.0f * ph * wl, &sn, &cs);
        fr[idx] = m*cs; fi[idx] = m*sn;
    }
    __syncthreads();
    // Stage A (rows)
    for (int idx = tid; idx < KK; idx += 256) {
        int u = idx / KSZ, j = idx % KSZ;
        float ar = 0.f, ai = 0.f;
        for (int i2 = 0; i2 < KSZ; i2++) {
            int t = (u*i2) % KSZ;
            float xr = fr[i2*KSZ + j], xi = fi[i2*KSZ + j];
            ar += xr*twr[t] - xi*twi[t];
            ai += xr*twi[t] + xi*twr[t];
        }
        gr2[idx] = ar; gi2[idx] = ai;
    }
    __syncthreads();
    // Stage B (cols) + power
    float psum = 0.f;
    for (int idx = tid; idx < KK; idx += 256) {
        int u = idx / KSZ, v = idx % KSZ;
        float ar = 0.f, ai = 0.f;
        for (int j2 = 0; j2 < KSZ; j2++) {
            int t = (v*j2) % KSZ;
            float xr = gr2[u*KSZ + j2], xi = gi2[u*KSZ + j2];
            ar += xr*twr[t] - xi*twi[t];
            ai += xr*twi[t] + xi*twr[t];
        }
        float p = ar*ar + ai*ai;
        fr[idx] = p;
        psum += p;
    }
    float tot = blockReduce256(psum, red);
    float inv = 1.0f / (tot + EPSF);
    for (int idx = tid; idx < KK; idx += 256) {
        int a = idx / KSZ, b = idx % KSZ;
        int sa = (15 - a + KSZ) % KSZ;
        int sb = (15 - b + KSZ) % KSZ;
        g_kern[(n*NC + c)*KK + idx] = fr[sa*KSZ + sb] * inv;
    }
}

// ---------------- Kernel 3: gamma linearize ----------------
__global__ void k_lin(const float* __restrict__ x, const float* __restrict__ gptr) {
    float g = *gptr;
    int total = NB*NC*HH*HH;
    for (int idx = blockIdx.x*blockDim.x + threadIdx.x; idx < total;
         idx += gridDim.x*blockDim.x)
        g_xlin[idx] = powf(fmaxf(x[idx], 0.0f) + EPSF, g);
}

// ---------------- Kernel 4: per-patch depthwise conv (hot loop) ----------------
// Skewed shared layout: logical col X at X + (X>>2) -> warp lanes (cols 4*tx)
// land on 5*tx mod 32 -> 32 distinct banks, conflict-free.
#define SRW 198
#define SHELEMS (PADD*SRW)

__global__ void __launch_bounds__(512, 1) k_conv() {
    extern __shared__ float sh[];
    float* ks = sh + SHELEMS;
    int n = blockIdx.x, c = blockIdx.y, b = blockIdx.z;
    int pi = n / NHP, pj = n % NHP;
    int tid = threadIdx.x;
    const float* src = g_xlin + ((size_t)(b*NC + c)*HH + (size_t)pi*STR)*HH + pj*STR;

    for (int idx = tid; idx < PADD*PADD; idx += 512) {
        int Y = idx / PADD, X = idx - Y*PADD;
        float v = 0.0f;
        int yy = Y - 15, xx = X - 15;
        if (yy >= 0 && yy < PSZ && xx >= 0 && xx < PSZ)
            v = src[yy*HH + xx];
        sh[Y*SRW + X + (X >> 2)] = v;
    }
    for (int t = tid; t < KK; t += 512)
        ks[t] = g_kern[(n*NC + c)*KK + t];
    __syncthreads();

    int tx = tid & 31, wy = tid >> 5;
    int py0 = wy * 8, px0 = tx * 4;
    int base0 = 5*tx;

    float acc[8][4];
    #pragma unroll
    for (int r = 0; r < 8; r++) { acc[r][0]=0.f; acc[r][1]=0.f; acc[r][2]=0.f; acc[r][3]=0.f; }

    for (int a = 0; a < KSZ; a++) {
        float kr[KSZ];
        #pragma unroll
        for (int q = 0; q < KSZ; q++) kr[q] = ks[a*KSZ + q];
        #pragma unroll
        for (int r = 0; r < 8; r++) {
            const float* row = sh + (py0 + r + a)*SRW + base0;
            float w0 = row[0], w1 = row[1], w2 = row[2], w3 = row[3];
            #pragma unroll
            for (int q = 0; q < KSZ; q++) {
                acc[r][0] += w0*kr[q];
                acc[r][1] += w1*kr[q];
                acc[r][2] += w2*kr[q];
                acc[r][3] += w3*kr[q];
                if (q < KSZ - 1) {
                    float wn = row[(4 + q) + ((4 + q) >> 2)];
                    w0 = w1; w1 = w2; w2 = w3; w3 = wn;
                }
            }
        }
    }

    float hx[4];
    #pragma unroll
    for (int j2 = 0; j2 < 4; j2++)
        hx[j2] = 0.5f*(1.0f - cospif((float)(px0 + j2) / 64.0f));
    size_t obase = ((size_t)((b*NPATCH + n)*NC + c)) * (PSZ*PSZ);
    #pragma unroll
    for (int r = 0; r < 8; r++) {
        float hy = 0.5f*(1.0f - cospif((float)(py0 + r) / 64.0f));
        float4 v4;
        v4.x = acc[r][0]*hy*hx[0];
        v4.y = acc[r][1]*hy*hx[1];
        v4.z = acc[r][2]*hy*hx[2];
        v4.w = acc[r][3]*hy*hx[3];
        *(float4*)&g_pout[obase + (size_t)(py0 + r)*PSZ + px0] = v4;
    }
}

// ---------------- Kernel 5: overlap-add gather + norm + gamma decode ----------------
__global__ void k_out(float* __restrict__ out, const float* __restrict__ gptr) {
    float ginv = 1.0f / *gptr;
    int total = NB*NC*HH*HH;
    for (int idx = blockIdx.x*blockDim.x + threadIdx.x; idx < total;
         idx += gridDim.x*blockDim.x) {
        int x = idx % HH;
        int y = (idx / HH) % HH;
        int c = (idx / (HH*HH)) % NC;
        int b =  idx / (HH*HH*NC);
        int i1 = y >> 6, j1 = x >> 6;
        int iis[2]; int ni = 0;
        if (i1 >= 1)  iis[ni++] = i1 - 1;
        if (i1 <= 10) iis[ni++] = i1;
        int jjs[2]; int nj = 0;
        if (j1 >= 1)  jjs[nj++] = j1 - 1;
        if (j1 <= 10) jjs[nj++] = j1;
        float ny = 0.f, nx = 0.f, s = 0.f;
        for (int ti = 0; ti < ni; ti++) {
            int py = y - 64*iis[ti];
            ny += 0.5f*(1.0f - cospif((float)py / 64.0f));
        }
        for (int tj = 0; tj < nj; tj++) {
            int px = x - 64*jjs[tj];
            nx += 0.5f*(1.0f - cospif((float)px / 64.0f));
        }
        for (int ti = 0; ti < ni; ti++)
            for (int tj = 0; tj < nj; tj++) {
                int pn = iis[ti]*NHP + jjs[tj];
                int py = y - 64*iis[ti], px = x - 64*jjs[tj];
                s += g_pout[((size_t)((b*NPATCH + pn)*NC + c))*(PSZ*PSZ) + py*PSZ + px];
            }
        float v = s / (ny*nx + EPSF);
        v = fmaxf(v, 0.0f);
        out[idx] = powf(v + EPSF, ginv);
    }
}

// ---------------- Launch ----------------
extern "C" void kernel_launch(void* const* d_in, const int* in_sizes, int n_in,
                              void* d_out, int out_size) {
    const float* x  = (const float*)d_in[0];
    const float* w1 = (const float*)d_in[1];
    const float* b1 = (const float*)d_in[2];
    const float* w2 = (const float*)d_in[3];
    const float* b2 = (const float*)d_in[4];
    const float* w3 = (const float*)d_in[5];
    const float* b3 = (const float*)d_in[6];
    const float* gm = (const float*)d_in[7];
    float* out = (float*)d_out;

    k_basis<<<1, 256>>>();
    k_mlp<<<1, 128>>>(w1, b1, w2, b2, w3, b3);
    k_psf<<<dim3(NPATCH, NC), 256>>>();
    k_lin<<<1024, 256>>>(x, gm);

    int smem = (SHELEMS + KK) * (int)sizeof(float);   // ~129 KB
    cudaFuncSetAttribute(k_conv, cudaFuncAttributeMaxDynamicSharedMemorySize, smem);
    k_conv<<<dim3(NPATCH, NC, NB), 512, smem>>>();

    k_out<<<2048, 256>>>(out, gm);
}